// round 14
// baseline (speedup 1.0000x reference)
#include <cuda_runtime.h>
#include <cuda_fp16.h>

// Problem constants
#define NB 4
#define NQ 256
#define NK 1024
#define ND 512
#define NH 256

// GEMM tiling
#define BM 64
#define BN 64
#define BK 16
#define KSPLIT 8
#define KCHUNK (NK / KSPLIT)   // 128

__device__ __align__(16) float   g_qproj[NB * NQ * NH];   // [bq][h]
__device__ __align__(16) __half2 g_kTh2[NB * NH * NK];    // [b][h][k] broadcast (k,k)
__device__ __align__(16) float   g_attn[NB * NQ * NK];    // [bq][k]
__device__ __align__(16) float   g_part[NB * KSPLIT * NQ * ND];  // split-K partials
__device__ float g_spacer_sink[32];

__device__ __forceinline__ __half2 h2tanh_fast(__half2 a) {
    __half2 r;
    asm("tanh.approx.f16x2 %0, %1;"
        : "=r"(*reinterpret_cast<unsigned int*>(&r))
        : "r"(*reinterpret_cast<unsigned int*>(&a)));
    return r;
}

__device__ __forceinline__ float cvt_tf32(float x) {
    unsigned u;
    asm("cvt.rna.tf32.f32 %0, %1;" : "=r"(u) : "f"(x));
    return __uint_as_float(u);
}

__device__ __forceinline__ void mma_tf32(float c[4], const unsigned a[4],
                                         const unsigned b[2]) {
    asm volatile(
        "mma.sync.aligned.m16n8k8.row.col.f32.tf32.tf32.f32 "
        "{%0,%1,%2,%3}, {%4,%5,%6,%7}, {%8,%9}, {%0,%1,%2,%3};"
        : "+f"(c[0]), "+f"(c[1]), "+f"(c[2]), "+f"(c[3])
        : "r"(a[0]), "r"(a[1]), "r"(a[2]), "r"(a[3]), "r"(b[0]), "r"(b[1]));
}

// packed fp32x2 helpers (sm_103a)
__device__ __forceinline__ unsigned long long pack_f32x2(float lo, float hi) {
    unsigned long long r;
    asm("mov.b64 %0, {%1, %2};" : "=l"(r) : "f"(lo), "f"(hi));
    return r;
}
__device__ __forceinline__ void unpack_f32x2(unsigned long long v, float& lo, float& hi) {
    asm("mov.b64 {%0, %1}, %2;" : "=f"(lo), "=f"(hi) : "l"(v));
}
__device__ __forceinline__ unsigned long long add_f32x2(unsigned long long a,
                                                        unsigned long long b) {
    unsigned long long r;
    asm("add.rn.f32x2 %0, %1, %2;" : "=l"(r) : "l"(a), "l"(b));
    return r;
}

// ---------------------------------------------------------------------------
// smem helpers (k-major [BK][64+4])
// ---------------------------------------------------------------------------
__device__ __forceinline__ void stsT_tf32(float S[BK][BM + 4], float4 v, int lk, int row) {
    S[lk + 0][row] = cvt_tf32(v.x);
    S[lk + 1][row] = cvt_tf32(v.y);
    S[lk + 2][row] = cvt_tf32(v.z);
    S[lk + 3][row] = cvt_tf32(v.w);
}

__device__ __forceinline__ float4 cvt4_tf32(float4 v) {
    return make_float4(cvt_tf32(v.x), cvt_tf32(v.y), cvt_tf32(v.z), cvt_tf32(v.w));
}

// tf32 mma over one BK=16 slab; warp tile 32x32 (2 m16 x 4 n8 x 2 k8)
__device__ __forceinline__ void mma_slab(const float As[BK][BM + 4],
                                         const float Bs[BK][BN + 4],
                                         float acc[2][4][4], int wr, int wc, int lane) {
    const int qk = lane & 3, qr = lane >> 2;
#pragma unroll
    for (int ks = 0; ks < BK; ks += 8) {
        unsigned a[2][4], b[4][2];
#pragma unroll
        for (int mt = 0; mt < 2; mt++) {
            const int r = wr + mt * 16 + qr;
            a[mt][0] = __float_as_uint(As[ks + qk][r]);
            a[mt][1] = __float_as_uint(As[ks + qk][r + 8]);
            a[mt][2] = __float_as_uint(As[ks + 4 + qk][r]);
            a[mt][3] = __float_as_uint(As[ks + 4 + qk][r + 8]);
        }
#pragma unroll
        for (int nt = 0; nt < 4; nt++) {
            const int n = wc + nt * 8 + qr;
            b[nt][0] = __float_as_uint(Bs[ks + qk][n]);
            b[nt][1] = __float_as_uint(Bs[ks + 4 + qk][n]);
        }
#pragma unroll
        for (int mt = 0; mt < 2; mt++)
#pragma unroll
            for (int nt = 0; nt < 4; nt++)
                mma_tf32(acc[mt][nt], a[mt], b[nt]);
    }
}

// ---------------------------------------------------------------------------
// Fused q/k projection (NT GEMMs) via tf32 tensor cores (single launch).
//  bid <  64 : qproj  C[bq][h]      (fp32 out)
//  bid >= 64 : kproj  kTh2[b][h][k] (broadcast (k,k) half2 out); dead tiles skipped
// ---------------------------------------------------------------------------
__global__ void __launch_bounds__(128) proj_gemm(const float* __restrict__ Qin,
                                                 const float* __restrict__ Kin,
                                                 const float* __restrict__ Wq,
                                                 const float* __restrict__ Wk,
                                                 const int* __restrict__ vlen) {
    __shared__ __align__(16) float As[BK][BM + 4];
    __shared__ __align__(16) float Bs[BK][BN + 4];
    const int K = 512;
    const int bid = blockIdx.x, tid = threadIdx.x;

    const float *A, *B;
    int m0, n0;
    const bool isq = bid < 64;
    if (isq) {
        m0 = (bid >> 2) * BM;  // 16 m-tiles over 1024 query rows
        n0 = (bid & 3) * BN;   // 4 n-tiles over 256 h
        A = Qin; B = Wq;
    } else {
        const int kb = bid - 64;
        m0 = (kb >> 6) * BM;   // 4 m-tiles over 256 h
        n0 = (kb & 63) * BN;   // 64 n-tiles over 4096 (b,k)
        if ((n0 & 1023) >= vlen[n0 >> 10]) return;   // dead k-tile
        A = Wk; B = Kin;
    }

    const int lr = tid >> 2;
    const int lk = (tid & 3) << 2;
    const float* Ap = A + (size_t)(m0 + lr) * K + lk;
    const float* Bp = B + (size_t)(n0 + lr) * K + lk;

    float4 a0 = *(const float4*)Ap;
    float4 a1 = *(const float4*)(Ap + 32 * K);
    float4 b0 = *(const float4*)Bp;
    float4 b1 = *(const float4*)(Bp + 32 * K);
    stsT_tf32(As, a0, lk, lr); stsT_tf32(As, a1, lk, lr + 32);
    stsT_tf32(Bs, b0, lk, lr); stsT_tf32(Bs, b1, lk, lr + 32);
    __syncthreads();

    float acc[2][4][4] = {};
    const int lane = tid & 31, wid = tid >> 5;
    const int wr = (wid & 1) * 32, wc = (wid >> 1) * 32;

    for (int k0 = BK; k0 < K; k0 += BK) {
        a0 = *(const float4*)(Ap + k0);
        a1 = *(const float4*)(Ap + 32 * K + k0);
        b0 = *(const float4*)(Bp + k0);
        b1 = *(const float4*)(Bp + 32 * K + k0);
        mma_slab(As, Bs, acc, wr, wc, lane);
        __syncthreads();
        stsT_tf32(As, a0, lk, lr); stsT_tf32(As, a1, lk, lr + 32);
        stsT_tf32(Bs, b0, lk, lr); stsT_tf32(Bs, b1, lk, lr + 32);
        __syncthreads();
    }
    mma_slab(As, Bs, acc, wr, wc, lane);

#pragma unroll
    for (int mt = 0; mt < 2; mt++) {
#pragma unroll
        for (int nt = 0; nt < 4; nt++) {
            const int r0 = m0 + wr + mt * 16 + (lane >> 2);
            const int cn = wc + nt * 8 + 2 * (lane & 3);
            if (isq) {
                *(float2*)&g_qproj[(size_t)r0 * NH + n0 + cn] =
                    make_float2(acc[mt][nt][0], acc[mt][nt][1]);
                *(float2*)&g_qproj[(size_t)(r0 + 8) * NH + n0 + cn] =
                    make_float2(acc[mt][nt][2], acc[mt][nt][3]);
            } else {
                // broadcast-duplicated fp16 store: element k -> half2 (k,k)
                const int gb = n0 >> 10;
                const int kx = (n0 & 1023) + cn;
                const __half h0 = __float2half_rn(acc[mt][nt][0]);
                const __half h1 = __float2half_rn(acc[mt][nt][1]);
                const __half h2 = __float2half_rn(acc[mt][nt][2]);
                const __half h3 = __float2half_rn(acc[mt][nt][3]);
                __half2* p0 = &g_kTh2[(size_t)(gb * NH + r0) * NK + kx];
                __half2* p1 = &g_kTh2[(size_t)(gb * NH + r0 + 8) * NK + kx];
                p0[0] = __halves2half2(h0, h0);
                p0[1] = __halves2half2(h1, h1);
                p1[0] = __halves2half2(h2, h2);
                p1[1] = __halves2half2(h3, h3);
            }
        }
    }
}

// Spacer: aligns the ncu capture (launch index 3) on scores_kernel.
__global__ void spacer_kernel() {
    if (threadIdx.x < 32) g_spacer_sink[threadIdx.x] = 1.0f;
}

// ---------------------------------------------------------------------------
// Scores + masked softmax. 512 blocks x 512 threads, 2 q-rows per block.
// Hot loop: LDG.64 broadcast keys + LDS.64 packed (q,w) + HFMA2 accumulation.
// ---------------------------------------------------------------------------
__global__ void __launch_bounds__(512) scores_kernel(const int* __restrict__ vlen,
                                                     const float* __restrict__ wv) {
    __shared__ float qsT[NH][2];
    __shared__ __align__(8) uint2 qw[NH];   // {q2(r0,r1), w2} per h
    __shared__ float wred[16][2];
    __shared__ float bred[2];

    const int tid = threadIdx.x;
    const int b = blockIdx.x >> 7;           // 128 blocks per batch
    const int q0 = (blockIdx.x & 127) << 1;  // 2 q rows per block
    const int vl = vlen[b];
    const int kb2 = tid * 2;

    {
        const int h = tid >> 1, r = tid & 1;
        qsT[h][r] = g_qproj[(size_t)(b * NQ + q0 + r) * NH + h];
    }
    __syncthreads();
    if (tid < NH) {
        const __half2 q2 = __floats2half2_rn(qsT[tid][0], qsT[tid][1]);
        const __half2 w2 = __float2half2_rn(wv[tid]);
        qw[tid] = make_uint2(*reinterpret_cast<const unsigned*>(&q2),
                             *reinterpret_cast<const unsigned*>(&w2));
    }
    __syncthreads();

    unsigned long long accf[2] = {};
    if (kb2 < vl) {   // fully-masked threads skip all loads + tanh work (exact)
        const __half2* kp = g_kTh2 + (size_t)b * NH * NK + kb2;
        const __half2 hz = __float2half2_rn(0.0f);
#pragma unroll 1
        for (int hc = 0; hc < NH; hc += 8) {
            __half2 acch0 = hz, acch1 = hz;
#pragma unroll
            for (int hh = 0; hh < 8; hh++) {
                const int h = hc + hh;
                // LDG.64: broadcast half2 for keys kb2 and kb2+1
                const uint2 kk = *reinterpret_cast<const uint2*>(kp + (size_t)h * NK);
                const __half2 k0 = *reinterpret_cast<const __half2*>(&kk.x);
                const __half2 k1 = *reinterpret_cast<const __half2*>(&kk.y);
                // LDS.64: packed q2/w2
                const uint2 qwv = qw[h];
                const __half2 q2 = *reinterpret_cast<const __half2*>(&qwv.x);
                const __half2 w2 = *reinterpret_cast<const __half2*>(&qwv.y);
                acch0 = __hfma2(w2, h2tanh_fast(__hadd2(q2, k0)), acch0);
                acch1 = __hfma2(w2, h2tanh_fast(__hadd2(q2, k1)), acch1);
            }
            const float2 f0 = __half22float2(acch0);
            const float2 f1 = __half22float2(acch1);
            accf[0] = add_f32x2(accf[0], pack_f32x2(f0.x, f0.y));
            accf[1] = add_f32x2(accf[1], pack_f32x2(f1.x, f1.y));
        }
    }

    float acc[2][2];
    unpack_f32x2(accf[0], acc[0][0], acc[1][0]);
    unpack_f32x2(accf[1], acc[0][1], acc[1][1]);

    float s0[2], s1[2], rm[2];
#pragma unroll
    for (int r = 0; r < 2; r++) {
        s0[r] = (kb2 < vl) ? acc[r][0] : -1e6f;
        s1[r] = (kb2 + 1 < vl) ? acc[r][1] : -1e6f;
        rm[r] = fmaxf(s0[r], s1[r]);
    }
#pragma unroll
    for (int o = 16; o > 0; o >>= 1)
#pragma unroll
        for (int r = 0; r < 2; r++)
            rm[r] = fmaxf(rm[r], __shfl_xor_sync(0xffffffffu, rm[r], o));
    const int wid = tid >> 5, lane = tid & 31;
    if (lane == 0)
#pragma unroll
        for (int r = 0; r < 2; r++) wred[wid][r] = rm[r];
    __syncthreads();
    if (tid < 2) {
        float m = wred[0][tid];
#pragma unroll
        for (int w2 = 1; w2 < 16; w2++) m = fmaxf(m, wred[w2][tid]);
        bred[tid] = m;
    }
    __syncthreads();

    float e0[2], e1[2], rs[2];
#pragma unroll
    for (int r = 0; r < 2; r++) {
        const float mx = bred[r];
        e0[r] = __expf(s0[r] - mx);
        e1[r] = __expf(s1[r] - mx);
        rs[r] = e0[r] + e1[r];
    }
#pragma unroll
    for (int o = 16; o > 0; o >>= 1)
#pragma unroll
        for (int r = 0; r < 2; r++)
            rs[r] += __shfl_xor_sync(0xffffffffu, rs[r], o);
    if (lane == 0)
#pragma unroll
        for (int r = 0; r < 2; r++) wred[wid][r] = rs[r];
    __syncthreads();
    if (tid < 2) {
        float s = 0.0f;
#pragma unroll
        for (int w2 = 0; w2 < 16; w2++) s += wred[w2][tid];
        bred[tid] = 1.0f / s;
    }
    __syncthreads();

    // av only reads attn for k < ceil(vl/KCHUNK)*KCHUNK — skip dead stores
    const int klim = ((vl + KCHUNK - 1) / KCHUNK) * KCHUNK;
    if (kb2 < klim) {
#pragma unroll
        for (int r = 0; r < 2; r++) {
            const float inv = bred[r];
            float2 o2 = make_float2(e0[r] * inv, e1[r] * inv);
            *reinterpret_cast<float2*>(&g_attn[(size_t)(b * NQ + q0 + r) * NK + kb2]) = o2;
        }
    }
}

// ---------------------------------------------------------------------------
// Split-K (x8) attn @ values via tf32 tensor cores; partials to g_part.
// ---------------------------------------------------------------------------
__global__ void __launch_bounds__(128) av_gemm(const float* __restrict__ V,
                                               const int* __restrict__ vlen) {
    __shared__ __align__(16) float As[BK][BM + 4];
    __shared__ __align__(16) float Bs[BK][BN + 4];
    const int tid = threadIdx.x;
    const int b = blockIdx.z >> 3;          // KSPLIT = 8
    const int split = blockIdx.z & 7;
    const int kbase = split * KCHUNK;
    if (kbase >= vlen[b]) return;   // partial is exactly zero; reduce skips it
    const int m0 = blockIdx.y * BM;
    const int n0 = blockIdx.x * BN;

    float acc[2][4][4] = {};
    const int lane = tid & 31, wid = tid >> 5;
    const int wr = (wid & 1) * 32, wc = (wid >> 1) * 32;

    const float* A = g_attn + (size_t)b * NQ * NK;
    const float* B = V + (size_t)b * NK * ND;

    const int lr = tid >> 2, lk = (tid & 3) << 2;   // A (transpose) loader
    const int bk = tid >> 4, bn = (tid & 15) << 2;  // B (direct) loader
    const float* Ap = A + (size_t)(m0 + lr) * NK + lk;
    const float* Bp = B + (size_t)bk * ND + n0 + bn;

    float4 a0 = *(const float4*)(Ap + kbase);
    float4 a1 = *(const float4*)(Ap + 32 * NK + kbase);
    float4 b0 = *(const float4*)(Bp + (size_t)kbase * ND);
    float4 b1 = *(const float4*)(Bp + (size_t)(kbase + 8) * ND);
    stsT_tf32(As, a0, lk, lr); stsT_tf32(As, a1, lk, lr + 32);
    *(float4*)&Bs[bk][bn] = cvt4_tf32(b0);
    *(float4*)&Bs[bk + 8][bn] = cvt4_tf32(b1);
    __syncthreads();

    for (int k0 = kbase + BK; k0 < kbase + KCHUNK; k0 += BK) {
        a0 = *(const float4*)(Ap + k0);
        a1 = *(const float4*)(Ap + 32 * NK + k0);
        b0 = *(const float4*)(Bp + (size_t)k0 * ND);
        b1 = *(const float4*)(Bp + (size_t)(k0 + 8) * ND);
        mma_slab(As, Bs, acc, wr, wc, lane);
        __syncthreads();
        stsT_tf32(As, a0, lk, lr); stsT_tf32(As, a1, lk, lr + 32);
        *(float4*)&Bs[bk][bn] = cvt4_tf32(b0);
        *(float4*)&Bs[bk + 8][bn] = cvt4_tf32(b1);
        __syncthreads();
    }
    mma_slab(As, Bs, acc, wr, wc, lane);

    float* P = g_part + (size_t)(b * KSPLIT + split) * NQ * ND;
#pragma unroll
    for (int mt = 0; mt < 2; mt++) {
#pragma unroll
        for (int nt = 0; nt < 4; nt++) {
            const int r0 = m0 + wr + mt * 16 + (lane >> 2);
            const int cn = n0 + wc + nt * 8 + 2 * (lane & 3);
            *(float2*)&P[(size_t)r0 * ND + cn] = make_float2(acc[mt][nt][0], acc[mt][nt][1]);
            *(float2*)&P[(size_t)(r0 + 8) * ND + cn] = make_float2(acc[mt][nt][2], acc[mt][nt][3]);
        }
    }
}

__global__ void __launch_bounds__(256) reduce_kernel(float* __restrict__ out,
                                                     const int* __restrict__ vlen) {
    const int i = blockIdx.x * 256 + threadIdx.x;   // float4 index, 131072 total
    const int b = i >> 15;
    const int off = i & 32767;
    const int nact = (vlen[b] + KCHUNK - 1) / KCHUNK;   // 1..KSPLIT active splits
    const float4* p = (const float4*)g_part;
    float4 s = p[(size_t)(b * KSPLIT + 0) * 32768 + off];
    for (int sp = 1; sp < nact; sp++) {
        const float4 t = p[(size_t)(b * KSPLIT + sp) * 32768 + off];
        s.x += t.x; s.y += t.y; s.z += t.z; s.w += t.w;
    }
    ((float4*)out)[i] = s;
}

// ---------------------------------------------------------------------------
extern "C" void kernel_launch(void* const* d_in, const int* in_sizes, int n_in,
                              void* d_out, int out_size) {
    const float* queries    = (const float*)d_in[0];
    const float* keys       = (const float*)d_in[1];
    const float* values     = (const float*)d_in[2];
    const int*   valid_lens = (const int*)d_in[3];
    const float* Wq         = (const float*)d_in[4];
    const float* Wk         = (const float*)d_in[5];
    const float* wv         = (const float*)d_in[6];
    float* out = (float*)d_out;

    (void)in_sizes; (void)n_in; (void)out_size;

    proj_gemm<<<320, 128>>>(queries, keys, Wq, Wk, valid_lens);  // 0: q+k proj
    spacer_kernel<<<1, 32>>>();                                  // 1: spacer
    spacer_kernel<<<1, 32>>>();                                  // 2: spacer
    scores_kernel<<<512, 512>>>(valid_lens, wv);                 // 3: scores (capture)
    av_gemm<<<dim3(ND / BN, NQ / BM, NB * KSPLIT), 128>>>(values, valid_lens);  // 4
    reduce_kernel<<<512, 256>>>(out, valid_lens);                // 5
}

// round 15
// speedup vs baseline: 1.0745x; 1.0745x over previous
#include <cuda_runtime.h>
#include <cuda_fp16.h>

// Problem constants
#define NB 4
#define NQ 256
#define NK 1024
#define ND 512
#define NH 256

// GEMM tiling
#define BM 64
#define BN 64
#define BK 16
#define KSPLIT 8
#define KCHUNK (NK / KSPLIT)   // 128

__device__ __align__(16) float  g_qproj[NB * NQ * NH];   // [bq][h]
__device__ __align__(16) __half g_kTh[NB * NH * NK];     // [b][h][k] fp16
__device__ __align__(16) float  g_attn[NB * NQ * NK];    // [bq][k]
__device__ __align__(16) float  g_part[NB * KSPLIT * NQ * ND];  // split-K partials
__device__ float g_spacer_sink[32];

__device__ __forceinline__ __half2 h2tanh_fast(__half2 a) {
    __half2 r;
    asm("tanh.approx.f16x2 %0, %1;"
        : "=r"(*reinterpret_cast<unsigned int*>(&r))
        : "r"(*reinterpret_cast<unsigned int*>(&a)));
    return r;
}

__device__ __forceinline__ float cvt_tf32(float x) {
    unsigned u;
    asm("cvt.rna.tf32.f32 %0, %1;" : "=r"(u) : "f"(x));
    return __uint_as_float(u);
}

__device__ __forceinline__ void mma_tf32(float c[4], const unsigned a[4],
                                         const unsigned b[2]) {
    asm volatile(
        "mma.sync.aligned.m16n8k8.row.col.f32.tf32.tf32.f32 "
        "{%0,%1,%2,%3}, {%4,%5,%6,%7}, {%8,%9}, {%0,%1,%2,%3};"
        : "+f"(c[0]), "+f"(c[1]), "+f"(c[2]), "+f"(c[3])
        : "r"(a[0]), "r"(a[1]), "r"(a[2]), "r"(a[3]), "r"(b[0]), "r"(b[1]));
}

// packed fp32x2 helpers (sm_103a)
__device__ __forceinline__ unsigned long long pack_f32x2(float lo, float hi) {
    unsigned long long r;
    asm("mov.b64 %0, {%1, %2};" : "=l"(r) : "f"(lo), "f"(hi));
    return r;
}
__device__ __forceinline__ void unpack_f32x2(unsigned long long v, float& lo, float& hi) {
    asm("mov.b64 {%0, %1}, %2;" : "=f"(lo), "=f"(hi) : "l"(v));
}
__device__ __forceinline__ unsigned long long add_f32x2(unsigned long long a,
                                                        unsigned long long b) {
    unsigned long long r;
    asm("add.rn.f32x2 %0, %1, %2;" : "=l"(r) : "l"(a), "l"(b));
    return r;
}

// ---------------------------------------------------------------------------
// smem helpers (k-major [BK][64+4])
// ---------------------------------------------------------------------------
__device__ __forceinline__ void stsT_tf32(float S[BK][BM + 4], float4 v, int lk, int row) {
    S[lk + 0][row] = cvt_tf32(v.x);
    S[lk + 1][row] = cvt_tf32(v.y);
    S[lk + 2][row] = cvt_tf32(v.z);
    S[lk + 3][row] = cvt_tf32(v.w);
}

__device__ __forceinline__ float4 cvt4_tf32(float4 v) {
    return make_float4(cvt_tf32(v.x), cvt_tf32(v.y), cvt_tf32(v.z), cvt_tf32(v.w));
}

// tf32 mma over one BK=16 slab; warp tile 32x32 (2 m16 x 4 n8 x 2 k8)
__device__ __forceinline__ void mma_slab(const float As[BK][BM + 4],
                                         const float Bs[BK][BN + 4],
                                         float acc[2][4][4], int wr, int wc, int lane) {
    const int qk = lane & 3, qr = lane >> 2;
#pragma unroll
    for (int ks = 0; ks < BK; ks += 8) {
        unsigned a[2][4], b[4][2];
#pragma unroll
        for (int mt = 0; mt < 2; mt++) {
            const int r = wr + mt * 16 + qr;
            a[mt][0] = __float_as_uint(As[ks + qk][r]);
            a[mt][1] = __float_as_uint(As[ks + qk][r + 8]);
            a[mt][2] = __float_as_uint(As[ks + 4 + qk][r]);
            a[mt][3] = __float_as_uint(As[ks + 4 + qk][r + 8]);
        }
#pragma unroll
        for (int nt = 0; nt < 4; nt++) {
            const int n = wc + nt * 8 + qr;
            b[nt][0] = __float_as_uint(Bs[ks + qk][n]);
            b[nt][1] = __float_as_uint(Bs[ks + 4 + qk][n]);
        }
#pragma unroll
        for (int mt = 0; mt < 2; mt++)
#pragma unroll
            for (int nt = 0; nt < 4; nt++)
                mma_tf32(acc[mt][nt], a[mt], b[nt]);
    }
}

// ---------------------------------------------------------------------------
// Fused q/k projection (NT GEMMs) via tf32 tensor cores (single launch).
//  bid <  64 : qproj  C[bq][h]     (fp32 out)
//  bid >= 64 : kproj  kTh[b][h][k] (fp16 out); dead k-tiles skipped
// ---------------------------------------------------------------------------
__global__ void __launch_bounds__(128) proj_gemm(const float* __restrict__ Qin,
                                                 const float* __restrict__ Kin,
                                                 const float* __restrict__ Wq,
                                                 const float* __restrict__ Wk,
                                                 const int* __restrict__ vlen) {
    __shared__ __align__(16) float As[BK][BM + 4];
    __shared__ __align__(16) float Bs[BK][BN + 4];
    const int K = 512;
    const int bid = blockIdx.x, tid = threadIdx.x;

    const float *A, *B;
    int m0, n0;
    const bool isq = bid < 64;
    if (isq) {
        m0 = (bid >> 2) * BM;  // 16 m-tiles over 1024 query rows
        n0 = (bid & 3) * BN;   // 4 n-tiles over 256 h
        A = Qin; B = Wq;
    } else {
        const int kb = bid - 64;
        m0 = (kb >> 6) * BM;   // 4 m-tiles over 256 h
        n0 = (kb & 63) * BN;   // 64 n-tiles over 4096 (b,k)
        if ((n0 & 1023) >= vlen[n0 >> 10]) return;   // dead k-tile
        A = Wk; B = Kin;
    }

    const int lr = tid >> 2;
    const int lk = (tid & 3) << 2;
    const float* Ap = A + (size_t)(m0 + lr) * K + lk;
    const float* Bp = B + (size_t)(n0 + lr) * K + lk;

    float4 a0 = *(const float4*)Ap;
    float4 a1 = *(const float4*)(Ap + 32 * K);
    float4 b0 = *(const float4*)Bp;
    float4 b1 = *(const float4*)(Bp + 32 * K);
    stsT_tf32(As, a0, lk, lr); stsT_tf32(As, a1, lk, lr + 32);
    stsT_tf32(Bs, b0, lk, lr); stsT_tf32(Bs, b1, lk, lr + 32);
    __syncthreads();

    float acc[2][4][4] = {};
    const int lane = tid & 31, wid = tid >> 5;
    const int wr = (wid & 1) * 32, wc = (wid >> 1) * 32;

    for (int k0 = BK; k0 < K; k0 += BK) {
        a0 = *(const float4*)(Ap + k0);
        a1 = *(const float4*)(Ap + 32 * K + k0);
        b0 = *(const float4*)(Bp + k0);
        b1 = *(const float4*)(Bp + 32 * K + k0);
        mma_slab(As, Bs, acc, wr, wc, lane);
        __syncthreads();
        stsT_tf32(As, a0, lk, lr); stsT_tf32(As, a1, lk, lr + 32);
        stsT_tf32(Bs, b0, lk, lr); stsT_tf32(Bs, b1, lk, lr + 32);
        __syncthreads();
    }
    mma_slab(As, Bs, acc, wr, wc, lane);

#pragma unroll
    for (int mt = 0; mt < 2; mt++) {
#pragma unroll
        for (int nt = 0; nt < 4; nt++) {
            const int r0 = m0 + wr + mt * 16 + (lane >> 2);
            const int cn = wc + nt * 8 + 2 * (lane & 3);
            if (isq) {
                *(float2*)&g_qproj[(size_t)r0 * NH + n0 + cn] =
                    make_float2(acc[mt][nt][0], acc[mt][nt][1]);
                *(float2*)&g_qproj[(size_t)(r0 + 8) * NH + n0 + cn] =
                    make_float2(acc[mt][nt][2], acc[mt][nt][3]);
            } else {
                const int gb = n0 >> 10;
                const int kx = (n0 & 1023) + cn;
                *(__half2*)&g_kTh[(size_t)(gb * NH + r0) * NK + kx] =
                    __floats2half2_rn(acc[mt][nt][0], acc[mt][nt][1]);
                *(__half2*)&g_kTh[(size_t)(gb * NH + r0 + 8) * NK + kx] =
                    __floats2half2_rn(acc[mt][nt][2], acc[mt][nt][3]);
            }
        }
    }
}

// Spacer: aligns the ncu capture (launch index 3) on scores_kernel.
__global__ void spacer_kernel() {
    if (threadIdx.x < 32) g_spacer_sink[threadIdx.x] = 1.0f;
}

// ---------------------------------------------------------------------------
// Scores + masked softmax. 512 blocks x 512 threads, 2 q-rows per block.
// Hot loop EXACTLY as the verified 36.9us round-13 version:
// LDG.32 fp16 keys + scalar qsh/wvh LDS + HFMA2 8-chunk accumulation.
// ---------------------------------------------------------------------------
__global__ void __launch_bounds__(512) scores_kernel(const int* __restrict__ vlen,
                                                     const float* __restrict__ wv) {
    __shared__ float qsT[NH][2];
    __shared__ __half2 qsh[NH];      // (r0,r1) per h
    __shared__ __half2 wvh[NH];
    __shared__ float wred[16][2];
    __shared__ float bred[2];

    const int tid = threadIdx.x;
    const int b = blockIdx.x >> 7;           // 128 blocks per batch
    const int q0 = (blockIdx.x & 127) << 1;  // 2 q rows per block
    const int vl = vlen[b];
    const int kb2 = tid * 2;

    if (tid < NH) wvh[tid] = __float2half2_rn(wv[tid]);
    {
        const int h = tid >> 1, r = tid & 1;
        qsT[h][r] = g_qproj[(size_t)(b * NQ + q0 + r) * NH + h];
    }
    __syncthreads();
    if (tid < NH) qsh[tid] = __floats2half2_rn(qsT[tid][0], qsT[tid][1]);
    __syncthreads();

    unsigned long long accf[2] = {};
    if (kb2 < vl) {   // fully-masked threads skip all loads + tanh work (exact)
        const __half2* kp = (const __half2*)g_kTh + (size_t)b * NH * (NK / 2) + tid;
        const __half2 hz = __float2half2_rn(0.0f);
#pragma unroll 1
        for (int hc = 0; hc < NH; hc += 8) {
            __half2 acch0 = hz, acch1 = hz;
#pragma unroll
            for (int hh = 0; hh < 8; hh++) {
                const int h = hc + hh;
                const __half2 kv2 = kp[(size_t)h * (NK / 2)];   // keys 2t, 2t+1
                const __half2 k0 = __low2half2(kv2);
                const __half2 k1 = __high2half2(kv2);
                const __half2 w2 = wvh[h];
                const __half2 q2 = qsh[h];
                acch0 = __hfma2(w2, h2tanh_fast(__hadd2(q2, k0)), acch0);
                acch1 = __hfma2(w2, h2tanh_fast(__hadd2(q2, k1)), acch1);
            }
            const float2 f0 = __half22float2(acch0);
            const float2 f1 = __half22float2(acch1);
            accf[0] = add_f32x2(accf[0], pack_f32x2(f0.x, f0.y));
            accf[1] = add_f32x2(accf[1], pack_f32x2(f1.x, f1.y));
        }
    }

    float acc[2][2];
    unpack_f32x2(accf[0], acc[0][0], acc[1][0]);
    unpack_f32x2(accf[1], acc[0][1], acc[1][1]);

    float s0[2], s1[2], rm[2];
#pragma unroll
    for (int r = 0; r < 2; r++) {
        s0[r] = (kb2 < vl) ? acc[r][0] : -1e6f;
        s1[r] = (kb2 + 1 < vl) ? acc[r][1] : -1e6f;
        rm[r] = fmaxf(s0[r], s1[r]);
    }
#pragma unroll
    for (int o = 16; o > 0; o >>= 1)
#pragma unroll
        for (int r = 0; r < 2; r++)
            rm[r] = fmaxf(rm[r], __shfl_xor_sync(0xffffffffu, rm[r], o));
    const int wid = tid >> 5, lane = tid & 31;
    if (lane == 0)
#pragma unroll
        for (int r = 0; r < 2; r++) wred[wid][r] = rm[r];
    __syncthreads();
    if (tid < 2) {
        float m = wred[0][tid];
#pragma unroll
        for (int w2 = 1; w2 < 16; w2++) m = fmaxf(m, wred[w2][tid]);
        bred[tid] = m;
    }
    __syncthreads();

    float e0[2], e1[2], rs[2];
#pragma unroll
    for (int r = 0; r < 2; r++) {
        const float mx = bred[r];
        e0[r] = __expf(s0[r] - mx);
        e1[r] = __expf(s1[r] - mx);
        rs[r] = e0[r] + e1[r];
    }
#pragma unroll
    for (int o = 16; o > 0; o >>= 1)
#pragma unroll
        for (int r = 0; r < 2; r++)
            rs[r] += __shfl_xor_sync(0xffffffffu, rs[r], o);
    if (lane == 0)
#pragma unroll
        for (int r = 0; r < 2; r++) wred[wid][r] = rs[r];
    __syncthreads();
    if (tid < 2) {
        float s = 0.0f;
#pragma unroll
        for (int w2 = 0; w2 < 16; w2++) s += wred[w2][tid];
        bred[tid] = 1.0f / s;
    }
    __syncthreads();

    // av only reads attn for k < ceil(vl/KCHUNK)*KCHUNK — skip dead stores
    const int klim = ((vl + KCHUNK - 1) / KCHUNK) * KCHUNK;
    if (kb2 < klim) {
#pragma unroll
        for (int r = 0; r < 2; r++) {
            const float inv = bred[r];
            float2 o2 = make_float2(e0[r] * inv, e1[r] * inv);
            *reinterpret_cast<float2*>(&g_attn[(size_t)(b * NQ + q0 + r) * NK + kb2]) = o2;
        }
    }
}

// ---------------------------------------------------------------------------
// Split-K (x8) attn @ values via tf32 tensor cores; partials to g_part.
// ---------------------------------------------------------------------------
__global__ void __launch_bounds__(128) av_gemm(const float* __restrict__ V,
                                               const int* __restrict__ vlen) {
    __shared__ __align__(16) float As[BK][BM + 4];
    __shared__ __align__(16) float Bs[BK][BN + 4];
    const int tid = threadIdx.x;
    const int b = blockIdx.z >> 3;          // KSPLIT = 8
    const int split = blockIdx.z & 7;
    const int kbase = split * KCHUNK;
    if (kbase >= vlen[b]) return;   // partial is exactly zero; reduce skips it
    const int m0 = blockIdx.y * BM;
    const int n0 = blockIdx.x * BN;

    float acc[2][4][4] = {};
    const int lane = tid & 31, wid = tid >> 5;
    const int wr = (wid & 1) * 32, wc = (wid >> 1) * 32;

    const float* A = g_attn + (size_t)b * NQ * NK;
    const float* B = V + (size_t)b * NK * ND;

    const int lr = tid >> 2, lk = (tid & 3) << 2;   // A (transpose) loader
    const int bk = tid >> 4, bn = (tid & 15) << 2;  // B (direct) loader
    const float* Ap = A + (size_t)(m0 + lr) * NK + lk;
    const float* Bp = B + (size_t)bk * ND + n0 + bn;

    float4 a0 = *(const float4*)(Ap + kbase);
    float4 a1 = *(const float4*)(Ap + 32 * NK + kbase);
    float4 b0 = *(const float4*)(Bp + (size_t)kbase * ND);
    float4 b1 = *(const float4*)(Bp + (size_t)(kbase + 8) * ND);
    stsT_tf32(As, a0, lk, lr); stsT_tf32(As, a1, lk, lr + 32);
    *(float4*)&Bs[bk][bn] = cvt4_tf32(b0);
    *(float4*)&Bs[bk + 8][bn] = cvt4_tf32(b1);
    __syncthreads();

    for (int k0 = kbase + BK; k0 < kbase + KCHUNK; k0 += BK) {
        a0 = *(const float4*)(Ap + k0);
        a1 = *(const float4*)(Ap + 32 * NK + k0);
        b0 = *(const float4*)(Bp + (size_t)k0 * ND);
        b1 = *(const float4*)(Bp + (size_t)(k0 + 8) * ND);
        mma_slab(As, Bs, acc, wr, wc, lane);
        __syncthreads();
        stsT_tf32(As, a0, lk, lr); stsT_tf32(As, a1, lk, lr + 32);
        *(float4*)&Bs[bk][bn] = cvt4_tf32(b0);
        *(float4*)&Bs[bk + 8][bn] = cvt4_tf32(b1);
        __syncthreads();
    }
    mma_slab(As, Bs, acc, wr, wc, lane);

    float* P = g_part + (size_t)(b * KSPLIT + split) * NQ * ND;
#pragma unroll
    for (int mt = 0; mt < 2; mt++) {
#pragma unroll
        for (int nt = 0; nt < 4; nt++) {
            const int r0 = m0 + wr + mt * 16 + (lane >> 2);
            const int cn = n0 + wc + nt * 8 + 2 * (lane & 3);
            *(float2*)&P[(size_t)r0 * ND + cn] = make_float2(acc[mt][nt][0], acc[mt][nt][1]);
            *(float2*)&P[(size_t)(r0 + 8) * ND + cn] = make_float2(acc[mt][nt][2], acc[mt][nt][3]);
        }
    }
}

__global__ void __launch_bounds__(256) reduce_kernel(float* __restrict__ out,
                                                     const int* __restrict__ vlen) {
    const int i = blockIdx.x * 256 + threadIdx.x;   // float4 index, 131072 total
    const int b = i >> 15;
    const int off = i & 32767;
    const int nact = (vlen[b] + KCHUNK - 1) / KCHUNK;   // 1..KSPLIT active splits
    const float4* p = (const float4*)g_part;
    float4 s = p[(size_t)(b * KSPLIT + 0) * 32768 + off];
    for (int sp = 1; sp < nact; sp++) {
        const float4 t = p[(size_t)(b * KSPLIT + sp) * 32768 + off];
        s.x += t.x; s.y += t.y; s.z += t.z; s.w += t.w;
    }
    ((float4*)out)[i] = s;
}

// ---------------------------------------------------------------------------
extern "C" void kernel_launch(void* const* d_in, const int* in_sizes, int n_in,
                              void* d_out, int out_size) {
    const float* queries    = (const float*)d_in[0];
    const float* keys       = (const float*)d_in[1];
    const float* values     = (const float*)d_in[2];
    const int*   valid_lens = (const int*)d_in[3];
    const float* Wq         = (const float*)d_in[4];
    const float* Wk         = (const float*)d_in[5];
    const float* wv         = (const float*)d_in[6];
    float* out = (float*)d_out;

    (void)in_sizes; (void)n_in; (void)out_size;

    proj_gemm<<<320, 128>>>(queries, keys, Wq, Wk, valid_lens);  // 0: q+k proj
    spacer_kernel<<<1, 32>>>();                                  // 1: spacer
    spacer_kernel<<<1, 32>>>();                                  // 2: spacer
    scores_kernel<<<512, 512>>>(valid_lens, wv);                 // 3: scores (capture)
    av_gemm<<<dim3(ND / BN, NQ / BM, NB * KSPLIT), 128>>>(values, valid_lens);  // 4
    reduce_kernel<<<512, 256>>>(out, valid_lens);                // 5
}

// round 16
// speedup vs baseline: 1.0838x; 1.0086x over previous
#include <cuda_runtime.h>
#include <cuda_fp16.h>

// Problem constants
#define NB 4
#define NQ 256
#define NK 1024
#define ND 512
#define NH 256

// GEMM tiling
#define BM 64
#define BN 64
#define BK 16
#define KSPLIT 8
#define KCHUNK (NK / KSPLIT)   // 128

__device__ __align__(16) float  g_qproj[NB * NQ * NH];   // [bq][h]
__device__ __align__(16) __half g_kTh[NB * NH * NK];     // [b][h][k] fp16
__device__ __align__(16) float  g_attn[NB * NQ * NK];    // [bq][k]
__device__ __align__(16) float  g_part[NB * KSPLIT * NQ * ND];  // split-K partials
__device__ float g_spacer_sink[32];

__device__ __forceinline__ __half2 h2tanh_fast(__half2 a) {
    __half2 r;
    asm("tanh.approx.f16x2 %0, %1;"
        : "=r"(*reinterpret_cast<unsigned int*>(&r))
        : "r"(*reinterpret_cast<unsigned int*>(&a)));
    return r;
}

__device__ __forceinline__ float cvt_tf32(float x) {
    unsigned u;
    asm("cvt.rna.tf32.f32 %0, %1;" : "=r"(u) : "f"(x));
    return __uint_as_float(u);
}

__device__ __forceinline__ void mma_tf32(float c[4], const unsigned a[4],
                                         const unsigned b[2]) {
    asm volatile(
        "mma.sync.aligned.m16n8k8.row.col.f32.tf32.tf32.f32 "
        "{%0,%1,%2,%3}, {%4,%5,%6,%7}, {%8,%9}, {%0,%1,%2,%3};"
        : "+f"(c[0]), "+f"(c[1]), "+f"(c[2]), "+f"(c[3])
        : "r"(a[0]), "r"(a[1]), "r"(a[2]), "r"(a[3]), "r"(b[0]), "r"(b[1]));
}

// packed fp32x2 helpers (sm_103a)
__device__ __forceinline__ unsigned long long pack_f32x2(float lo, float hi) {
    unsigned long long r;
    asm("mov.b64 %0, {%1, %2};" : "=l"(r) : "f"(lo), "f"(hi));
    return r;
}
__device__ __forceinline__ void unpack_f32x2(unsigned long long v, float& lo, float& hi) {
    asm("mov.b64 {%0, %1}, %2;" : "=f"(lo), "=f"(hi) : "l"(v));
}
__device__ __forceinline__ unsigned long long add_f32x2(unsigned long long a,
                                                        unsigned long long b) {
    unsigned long long r;
    asm("add.rn.f32x2 %0, %1, %2;" : "=l"(r) : "l"(a), "l"(b));
    return r;
}

// ---------------------------------------------------------------------------
// smem helpers (k-major [BK][64+4])
// ---------------------------------------------------------------------------
__device__ __forceinline__ void stsT_tf32(float S[BK][BM + 4], float4 v, int lk, int row) {
    S[lk + 0][row] = cvt_tf32(v.x);
    S[lk + 1][row] = cvt_tf32(v.y);
    S[lk + 2][row] = cvt_tf32(v.z);
    S[lk + 3][row] = cvt_tf32(v.w);
}

__device__ __forceinline__ float4 cvt4_tf32(float4 v) {
    return make_float4(cvt_tf32(v.x), cvt_tf32(v.y), cvt_tf32(v.z), cvt_tf32(v.w));
}

// tf32 mma over one BK=16 slab; warp tile 32x32 (2 m16 x 4 n8 x 2 k8) — av kernel
__device__ __forceinline__ void mma_slab(const float As[BK][BM + 4],
                                         const float Bs[BK][BN + 4],
                                         float acc[2][4][4], int wr, int wc, int lane) {
    const int qk = lane & 3, qr = lane >> 2;
#pragma unroll
    for (int ks = 0; ks < BK; ks += 8) {
        unsigned a[2][4], b[4][2];
#pragma unroll
        for (int mt = 0; mt < 2; mt++) {
            const int r = wr + mt * 16 + qr;
            a[mt][0] = __float_as_uint(As[ks + qk][r]);
            a[mt][1] = __float_as_uint(As[ks + qk][r + 8]);
            a[mt][2] = __float_as_uint(As[ks + 4 + qk][r]);
            a[mt][3] = __float_as_uint(As[ks + 4 + qk][r + 8]);
        }
#pragma unroll
        for (int nt = 0; nt < 4; nt++) {
            const int n = wc + nt * 8 + qr;
            b[nt][0] = __float_as_uint(Bs[ks + qk][n]);
            b[nt][1] = __float_as_uint(Bs[ks + 4 + qk][n]);
        }
#pragma unroll
        for (int mt = 0; mt < 2; mt++)
#pragma unroll
            for (int nt = 0; nt < 4; nt++)
                mma_tf32(acc[mt][nt], a[mt], b[nt]);
    }
}

// tf32 mma over one BK=16 slab; warp tile 32x16 (2 m16 x 2 n8 x 2 k8) — proj kernel
__device__ __forceinline__ void mma_slab16(const float As[BK][BM + 4],
                                           const float Bs[BK][BN + 4],
                                           float acc[2][2][4], int wr, int wc, int lane) {
    const int qk = lane & 3, qr = lane >> 2;
#pragma unroll
    for (int ks = 0; ks < BK; ks += 8) {
        unsigned a[2][4], b[2][2];
#pragma unroll
        for (int mt = 0; mt < 2; mt++) {
            const int r = wr + mt * 16 + qr;
            a[mt][0] = __float_as_uint(As[ks + qk][r]);
            a[mt][1] = __float_as_uint(As[ks + qk][r + 8]);
            a[mt][2] = __float_as_uint(As[ks + 4 + qk][r]);
            a[mt][3] = __float_as_uint(As[ks + 4 + qk][r + 8]);
        }
#pragma unroll
        for (int nt = 0; nt < 2; nt++) {
            const int n = wc + nt * 8 + qr;
            b[nt][0] = __float_as_uint(Bs[ks + qk][n]);
            b[nt][1] = __float_as_uint(Bs[ks + 4 + qk][n]);
        }
#pragma unroll
        for (int mt = 0; mt < 2; mt++)
#pragma unroll
            for (int nt = 0; nt < 2; nt++)
                mma_tf32(acc[mt][nt], a[mt], b[nt]);
    }
}

// ---------------------------------------------------------------------------
// Fused q/k projection (NT GEMMs) via tf32 tensor cores.
// 256 threads (8 warps, warp tile 32x16), double-buffered smem (1 BAR/iter).
//  bid <  64 : qproj  C[bq][h]     (fp32 out)
//  bid >= 64 : kproj  kTh[b][h][k] (fp16 out); dead k-tiles skipped
// ---------------------------------------------------------------------------
__global__ void __launch_bounds__(256) proj_gemm(const float* __restrict__ Qin,
                                                 const float* __restrict__ Kin,
                                                 const float* __restrict__ Wq,
                                                 const float* __restrict__ Wk,
                                                 const int* __restrict__ vlen) {
    __shared__ __align__(16) float As[2][BK][BM + 4];
    __shared__ __align__(16) float Bs[2][BK][BN + 4];
    const int K = 512;
    const int bid = blockIdx.x, tid = threadIdx.x;

    const float *A, *B;
    int m0, n0;
    const bool isq = bid < 64;
    if (isq) {
        m0 = (bid >> 2) * BM;  // 16 m-tiles over 1024 query rows
        n0 = (bid & 3) * BN;   // 4 n-tiles over 256 h
        A = Qin; B = Wq;
    } else {
        const int kb = bid - 64;
        m0 = (kb >> 6) * BM;   // 4 m-tiles over 256 h
        n0 = (kb & 63) * BN;   // 64 n-tiles over 4096 (b,k)
        if ((n0 & 1023) >= vlen[n0 >> 10]) return;   // dead k-tile
        A = Wk; B = Kin;
    }

    const int lr = tid >> 2;          // 0..63 (one row per 4 threads)
    const int lk = (tid & 3) << 2;    // 0,4,8,12
    const float* Ap = A + (size_t)(m0 + lr) * K + lk;
    const float* Bp = B + (size_t)(n0 + lr) * K + lk;

    float4 a0 = *(const float4*)Ap;
    float4 b0 = *(const float4*)Bp;
    stsT_tf32(As[0], a0, lk, lr);
    stsT_tf32(Bs[0], b0, lk, lr);
    __syncthreads();

    float acc[2][2][4] = {};
    const int lane = tid & 31, wid = tid >> 5;
    const int wr = (wid & 1) * 32;    // 2 warp rows of 32
    const int wc = (wid >> 1) * 16;   // 4 warp cols of 16

    int buf = 0;
    for (int k0 = BK; k0 < K; k0 += BK) {
        a0 = *(const float4*)(Ap + k0);
        b0 = *(const float4*)(Bp + k0);
        mma_slab16(As[buf], Bs[buf], acc, wr, wc, lane);
        stsT_tf32(As[buf ^ 1], a0, lk, lr);   // write other buffer — no pre-barrier
        stsT_tf32(Bs[buf ^ 1], b0, lk, lr);
        __syncthreads();
        buf ^= 1;
    }
    mma_slab16(As[buf], Bs[buf], acc, wr, wc, lane);

#pragma unroll
    for (int mt = 0; mt < 2; mt++) {
#pragma unroll
        for (int nt = 0; nt < 2; nt++) {
            const int r0 = m0 + wr + mt * 16 + (lane >> 2);
            const int cn = wc + nt * 8 + 2 * (lane & 3);
            if (isq) {
                *(float2*)&g_qproj[(size_t)r0 * NH + n0 + cn] =
                    make_float2(acc[mt][nt][0], acc[mt][nt][1]);
                *(float2*)&g_qproj[(size_t)(r0 + 8) * NH + n0 + cn] =
                    make_float2(acc[mt][nt][2], acc[mt][nt][3]);
            } else {
                const int gb = n0 >> 10;
                const int kx = (n0 & 1023) + cn;
                *(__half2*)&g_kTh[(size_t)(gb * NH + r0) * NK + kx] =
                    __floats2half2_rn(acc[mt][nt][0], acc[mt][nt][1]);
                *(__half2*)&g_kTh[(size_t)(gb * NH + r0 + 8) * NK + kx] =
                    __floats2half2_rn(acc[mt][nt][2], acc[mt][nt][3]);
            }
        }
    }
}

// Spacer: three copies before proj_gemm put it at ncu capture index 3.
__global__ void spacer_kernel() {
    if (threadIdx.x < 32) g_spacer_sink[threadIdx.x] = 1.0f;
}

// ---------------------------------------------------------------------------
// Scores + masked softmax. 512 blocks x 512 threads, 2 q-rows per block.
// (UNCHANGED — verified 36.7us, at its MUFU floor.)
// ---------------------------------------------------------------------------
__global__ void __launch_bounds__(512) scores_kernel(const int* __restrict__ vlen,
                                                     const float* __restrict__ wv) {
    __shared__ float qsT[NH][2];
    __shared__ __half2 qsh[NH];      // (r0,r1) per h
    __shared__ __half2 wvh[NH];
    __shared__ float wred[16][2];
    __shared__ float bred[2];

    const int tid = threadIdx.x;
    const int b = blockIdx.x >> 7;           // 128 blocks per batch
    const int q0 = (blockIdx.x & 127) << 1;  // 2 q rows per block
    const int vl = vlen[b];
    const int kb2 = tid * 2;

    if (tid < NH) wvh[tid] = __float2half2_rn(wv[tid]);
    {
        const int h = tid >> 1, r = tid & 1;
        qsT[h][r] = g_qproj[(size_t)(b * NQ + q0 + r) * NH + h];
    }
    __syncthreads();
    if (tid < NH) qsh[tid] = __floats2half2_rn(qsT[tid][0], qsT[tid][1]);
    __syncthreads();

    unsigned long long accf[2] = {};
    if (kb2 < vl) {   // fully-masked threads skip all loads + tanh work (exact)
        const __half2* kp = (const __half2*)g_kTh + (size_t)b * NH * (NK / 2) + tid;
        const __half2 hz = __float2half2_rn(0.0f);
#pragma unroll 1
        for (int hc = 0; hc < NH; hc += 8) {
            __half2 acch0 = hz, acch1 = hz;
#pragma unroll
            for (int hh = 0; hh < 8; hh++) {
                const int h = hc + hh;
                const __half2 kv2 = kp[(size_t)h * (NK / 2)];   // keys 2t, 2t+1
                const __half2 k0 = __low2half2(kv2);
                const __half2 k1 = __high2half2(kv2);
                const __half2 w2 = wvh[h];
                const __half2 q2 = qsh[h];
                acch0 = __hfma2(w2, h2tanh_fast(__hadd2(q2, k0)), acch0);
                acch1 = __hfma2(w2, h2tanh_fast(__hadd2(q2, k1)), acch1);
            }
            const float2 f0 = __half22float2(acch0);
            const float2 f1 = __half22float2(acch1);
            accf[0] = add_f32x2(accf[0], pack_f32x2(f0.x, f0.y));
            accf[1] = add_f32x2(accf[1], pack_f32x2(f1.x, f1.y));
        }
    }

    float acc[2][2];
    unpack_f32x2(accf[0], acc[0][0], acc[1][0]);
    unpack_f32x2(accf[1], acc[0][1], acc[1][1]);

    float s0[2], s1[2], rm[2];
#pragma unroll
    for (int r = 0; r < 2; r++) {
        s0[r] = (kb2 < vl) ? acc[r][0] : -1e6f;
        s1[r] = (kb2 + 1 < vl) ? acc[r][1] : -1e6f;
        rm[r] = fmaxf(s0[r], s1[r]);
    }
#pragma unroll
    for (int o = 16; o > 0; o >>= 1)
#pragma unroll
        for (int r = 0; r < 2; r++)
            rm[r] = fmaxf(rm[r], __shfl_xor_sync(0xffffffffu, rm[r], o));
    const int wid = tid >> 5, lane = tid & 31;
    if (lane == 0)
#pragma unroll
        for (int r = 0; r < 2; r++) wred[wid][r] = rm[r];
    __syncthreads();
    if (tid < 2) {
        float m = wred[0][tid];
#pragma unroll
        for (int w2 = 1; w2 < 16; w2++) m = fmaxf(m, wred[w2][tid]);
        bred[tid] = m;
    }
    __syncthreads();

    float e0[2], e1[2], rs[2];
#pragma unroll
    for (int r = 0; r < 2; r++) {
        const float mx = bred[r];
        e0[r] = __expf(s0[r] - mx);
        e1[r] = __expf(s1[r] - mx);
        rs[r] = e0[r] + e1[r];
    }
#pragma unroll
    for (int o = 16; o > 0; o >>= 1)
#pragma unroll
        for (int r = 0; r < 2; r++)
            rs[r] += __shfl_xor_sync(0xffffffffu, rs[r], o);
    if (lane == 0)
#pragma unroll
        for (int r = 0; r < 2; r++) wred[wid][r] = rs[r];
    __syncthreads();
    if (tid < 2) {
        float s = 0.0f;
#pragma unroll
        for (int w2 = 0; w2 < 16; w2++) s += wred[w2][tid];
        bred[tid] = 1.0f / s;
    }
    __syncthreads();

    // av only reads attn for k < ceil(vl/KCHUNK)*KCHUNK — skip dead stores
    const int klim = ((vl + KCHUNK - 1) / KCHUNK) * KCHUNK;
    if (kb2 < klim) {
#pragma unroll
        for (int r = 0; r < 2; r++) {
            const float inv = bred[r];
            float2 o2 = make_float2(e0[r] * inv, e1[r] * inv);
            *reinterpret_cast<float2*>(&g_attn[(size_t)(b * NQ + q0 + r) * NK + kb2]) = o2;
        }
    }
}

// ---------------------------------------------------------------------------
// Split-K (x8) attn @ values via tf32 tensor cores; partials to g_part.
// ---------------------------------------------------------------------------
__global__ void __launch_bounds__(128) av_gemm(const float* __restrict__ V,
                                               const int* __restrict__ vlen) {
    __shared__ __align__(16) float As[BK][BM + 4];
    __shared__ __align__(16) float Bs[BK][BN + 4];
    const int tid = threadIdx.x;
    const int b = blockIdx.z >> 3;          // KSPLIT = 8
    const int split = blockIdx.z & 7;
    const int kbase = split * KCHUNK;
    if (kbase >= vlen[b]) return;   // partial is exactly zero; reduce skips it
    const int m0 = blockIdx.y * BM;
    const int n0 = blockIdx.x * BN;

    float acc[2][4][4] = {};
    const int lane = tid & 31, wid = tid >> 5;
    const int wr = (wid & 1) * 32, wc = (wid >> 1) * 32;

    const float* A = g_attn + (size_t)b * NQ * NK;
    const float* B = V + (size_t)b * NK * ND;

    const int lr = tid >> 2, lk = (tid & 3) << 2;   // A (transpose) loader
    const int bk = tid >> 4, bn = (tid & 15) << 2;  // B (direct) loader
    const float* Ap = A + (size_t)(m0 + lr) * NK + lk;
    const float* Bp = B + (size_t)bk * ND + n0 + bn;

    float4 a0 = *(const float4*)(Ap + kbase);
    float4 a1 = *(const float4*)(Ap + 32 * NK + kbase);
    float4 b0 = *(const float4*)(Bp + (size_t)kbase * ND);
    float4 b1 = *(const float4*)(Bp + (size_t)(kbase + 8) * ND);
    stsT_tf32(As, a0, lk, lr); stsT_tf32(As, a1, lk, lr + 32);
    *(float4*)&Bs[bk][bn] = cvt4_tf32(b0);
    *(float4*)&Bs[bk + 8][bn] = cvt4_tf32(b1);
    __syncthreads();

    for (int k0 = kbase + BK; k0 < kbase + KCHUNK; k0 += BK) {
        a0 = *(const float4*)(Ap + k0);
        a1 = *(const float4*)(Ap + 32 * NK + k0);
        b0 = *(const float4*)(Bp + (size_t)k0 * ND);
        b1 = *(const float4*)(Bp + (size_t)(k0 + 8) * ND);
        mma_slab(As, Bs, acc, wr, wc, lane);
        __syncthreads();
        stsT_tf32(As, a0, lk, lr); stsT_tf32(As, a1, lk, lr + 32);
        *(float4*)&Bs[bk][bn] = cvt4_tf32(b0);
        *(float4*)&Bs[bk + 8][bn] = cvt4_tf32(b1);
        __syncthreads();
    }
    mma_slab(As, Bs, acc, wr, wc, lane);

    float* P = g_part + (size_t)(b * KSPLIT + split) * NQ * ND;
#pragma unroll
    for (int mt = 0; mt < 2; mt++) {
#pragma unroll
        for (int nt = 0; nt < 4; nt++) {
            const int r0 = m0 + wr + mt * 16 + (lane >> 2);
            const int cn = n0 + wc + nt * 8 + 2 * (lane & 3);
            *(float2*)&P[(size_t)r0 * ND + cn] = make_float2(acc[mt][nt][0], acc[mt][nt][1]);
            *(float2*)&P[(size_t)(r0 + 8) * ND + cn] = make_float2(acc[mt][nt][2], acc[mt][nt][3]);
        }
    }
}

__global__ void __launch_bounds__(256) reduce_kernel(float* __restrict__ out,
                                                     const int* __restrict__ vlen) {
    const int i = blockIdx.x * 256 + threadIdx.x;   // float4 index, 131072 total
    const int b = i >> 15;
    const int off = i & 32767;
    const int nact = (vlen[b] + KCHUNK - 1) / KCHUNK;   // 1..KSPLIT active splits
    const float4* p = (const float4*)g_part;
    float4 s = p[(size_t)(b * KSPLIT + 0) * 32768 + off];
    for (int sp = 1; sp < nact; sp++) {
        const float4 t = p[(size_t)(b * KSPLIT + sp) * 32768 + off];
        s.x += t.x; s.y += t.y; s.z += t.z; s.w += t.w;
    }
    ((float4*)out)[i] = s;
}

// ---------------------------------------------------------------------------
extern "C" void kernel_launch(void* const* d_in, const int* in_sizes, int n_in,
                              void* d_out, int out_size) {
    const float* queries    = (const float*)d_in[0];
    const float* keys       = (const float*)d_in[1];
    const float* values     = (const float*)d_in[2];
    const int*   valid_lens = (const int*)d_in[3];
    const float* Wq         = (const float*)d_in[4];
    const float* Wk         = (const float*)d_in[5];
    const float* wv         = (const float*)d_in[6];
    float* out = (float*)d_out;

    (void)in_sizes; (void)n_in; (void)out_size;

    spacer_kernel<<<1, 32>>>();                                  // 0: spacer
    spacer_kernel<<<1, 32>>>();                                  // 1: spacer
    spacer_kernel<<<1, 32>>>();                                  // 2: spacer
    proj_gemm<<<320, 256>>>(queries, keys, Wq, Wk, valid_lens);  // 3: proj (capture)
    scores_kernel<<<512, 512>>>(valid_lens, wv);                 // 4: scores
    av_gemm<<<dim3(ND / BN, NQ / BM, NB * KSPLIT), 128>>>(values, valid_lens);  // 5
    reduce_kernel<<<512, 256>>>(out, valid_lens);                // 6
}